// round 8
// baseline (speedup 1.0000x reference)
#include <cuda_runtime.h>
#include <math.h>

// Split-KV (flash-decoding) stage-2 merge. B=256, H=32, S=16, D=128, fp32.
//
// R7 design (from R5/R6 evidence: latency-bound, nothing saturated, more
// warps always won):
//   * TWO warps per head, interleaved splits (warp j takes s = j, j+2, ...)
//     -> 16384 warps, per-warp load chain halved (max 2 four-wide batches)
//   * LSE load UNCONDITIONAL -> issues in parallel with the div chain
//   * 4-step low-half xor reductions + single broadcast (not 5-step full-warp)
//   * weights replicated in both warps (no sync on the stats path);
//     only the accumulator is combined: odd warp STS 512B -> bar -> even
//     warp LDS+add+scale+STG
//   * per-load predication exact -> traffic unchanged (~38MB effective)

#define B_DIM 256
#define H_DIM 32
#define S_DIM 16
#define D_DIM 128
#define LOG2E 1.4426950408889634f

__global__ __launch_bounds__(128)
void splitkv_merge_kernel(const float* __restrict__ att_out,
                          const float* __restrict__ att_lse,
                          const int*   __restrict__ kv_indptr,
                          const int*   __restrict__ num_kv_splits,
                          float*       __restrict__ out)
{
    // 128 threads = 4 warps = 2 heads per block (2 warps per head)
    __shared__ float4 part[2][32];           // odd-warp partial accumulators

    const unsigned tid   = threadIdx.x;
    const unsigned lane  = tid & 31u;
    const unsigned hid   = (blockIdx.x * 128u + tid) >> 6;   // global head id
    const unsigned j     = (tid >> 5) & 1u;                  // warp-in-head: 0/1
    const unsigned hloc  = tid >> 6;                         // head-in-block: 0/1
    const unsigned b     = hid >> 5;                         // H_DIM == 32

    // ---- LSE load FIRST, unconditional: independent of the geometry chain ----
    float lse_raw = 0.0f;
    if (lane < 16u)
        lse_raw = att_lse[hid * 16u + lane];

    // ---- geometry (warp-uniform, unsigned div) ----
    const unsigned seq_len = (unsigned)(kv_indptr[b + 1] - kv_indptr[b]);
    const unsigned splits  = (unsigned)num_kv_splits[b];
    const unsigned per_split = ((((seq_len + splits - 1u) / splits) + 31u) >> 5) << 5;
    const unsigned nv = (seq_len + per_split - 1u) / per_split;   // 1..16 prefix

    // ---- weights: 4-step reductions over lanes 0-15 only ----
    float lse = (lane < nv) ? lse_raw : -INFINITY;

    float m = lse;
    #pragma unroll
    for (int o = 8; o > 0; o >>= 1)
        m = fmaxf(m, __shfl_xor_sync(0xffffffffu, m, o));

    float w = (lane < nv) ? exp2f((lse - m) * LOG2E) : 0.0f;

    float esum = w;
    #pragma unroll
    for (int o = 8; o > 0; o >>= 1)
        esum += __shfl_xor_sync(0xffffffffu, esum, o);

    const float inv_esum = __shfl_sync(0xffffffffu, 1.0f / esum, 0);

    // ---- accumulate my interleaved splits: s = j + 2k, k = 0..7 ----
    const float4* __restrict__ src =
        reinterpret_cast<const float4*>(att_out) + hid * 512u + lane;

    float4 acc = make_float4(0.f, 0.f, 0.f, 0.f);

    #pragma unroll
    for (int k0 = 0; k0 < 8; k0 += 4) {
        const int sbase = (int)j + 2 * k0;          // first s of this batch
        if (sbase < (int)nv) {                      // warp-uniform batch skip
            float4 v0, v1, v2, v3;
            v0 = v1 = v2 = v3 = make_float4(0.f, 0.f, 0.f, 0.f);
            // front-batched predicated loads: 4 x LDG.E.128
            if (sbase + 0 < (int)nv) v0 = src[(sbase + 0) * 32];
            if (sbase + 2 < (int)nv) v1 = src[(sbase + 2) * 32];
            if (sbase + 4 < (int)nv) v2 = src[(sbase + 4) * 32];
            if (sbase + 6 < (int)nv) v3 = src[(sbase + 6) * 32];

            float ws;
            ws = __shfl_sync(0xffffffffu, w, sbase + 0);
            acc.x = fmaf(ws, v0.x, acc.x); acc.y = fmaf(ws, v0.y, acc.y);
            acc.z = fmaf(ws, v0.z, acc.z); acc.w = fmaf(ws, v0.w, acc.w);
            ws = __shfl_sync(0xffffffffu, w, sbase + 2);
            acc.x = fmaf(ws, v1.x, acc.x); acc.y = fmaf(ws, v1.y, acc.y);
            acc.z = fmaf(ws, v1.z, acc.z); acc.w = fmaf(ws, v1.w, acc.w);
            ws = __shfl_sync(0xffffffffu, w, sbase + 4);
            acc.x = fmaf(ws, v2.x, acc.x); acc.y = fmaf(ws, v2.y, acc.y);
            acc.z = fmaf(ws, v2.z, acc.z); acc.w = fmaf(ws, v2.w, acc.w);
            ws = __shfl_sync(0xffffffffu, w, sbase + 6);
            acc.x = fmaf(ws, v3.x, acc.x); acc.y = fmaf(ws, v3.y, acc.y);
            acc.z = fmaf(ws, v3.z, acc.z); acc.w = fmaf(ws, v3.w, acc.w);
        }
    }

    // ---- combine the two warps' partials through smem ----
    if (j == 1u)
        part[hloc][lane] = acc;
    __syncthreads();

    if (j == 0u) {
        const float4 p = part[hloc][lane];
        acc.x = (acc.x + p.x) * inv_esum;
        acc.y = (acc.y + p.y) * inv_esum;
        acc.z = (acc.z + p.z) * inv_esum;
        acc.w = (acc.w + p.w) * inv_esum;
        reinterpret_cast<float4*>(out)[hid * 32u + lane] = acc;
    }
}

extern "C" void kernel_launch(void* const* d_in, const int* in_sizes, int n_in,
                              void* d_out, int out_size)
{
    const float* att_out       = (const float*)d_in[0];
    const float* att_lse       = (const float*)d_in[1];
    // d_in[2] = q, d_in[3] = v_buffer : unused (shape-only in the reference)
    const int*   kv_indptr     = (const int*)d_in[4];
    const int*   num_kv_splits = (const int*)d_in[5];
    float*       out           = (float*)d_out;

    // 8192 heads x 2 warps = 16384 warps; 4 warps/block -> 4096 blocks exact
    splitkv_merge_kernel<<<(B_DIM * H_DIM * 2) / 4, 128>>>(att_out, att_lse,
                                                           kv_indptr, num_kv_splits, out);
}

// round 9
// speedup vs baseline: 1.0031x; 1.0031x over previous
#include <cuda_runtime.h>
#include <math.h>

// Split-KV (flash-decoding) stage-2 merge. B=256, H=32, S=16, D=128, fp32.
//
// R8 design (R5 shape kept: 1 warp/head, 8192 warps, 4-wide predicated
// batches; attack is purely the per-warp serial chain):
//   * s=0,1 att_out rows + full LSE row issued UNCONDITIONALLY at cycle 0,
//     overlapping the whole geometry/weight prologue with DRAM latency
//     (s=1 invalid only when nv==1 -> w=0 kills it; ~1MB extra traffic)
//   * NO shuffle reductions: every lane loads the 16-float LSE row
//     (uniform float4 loads = broadcast) and reduces in registers
//     (tree depth 4, ~16cyc vs ~130cyc per 5-step SHFL chain); every lane
//     then holds all 16 weights -> zero SHFLs in the FMA loop too
//   * ceil-divisions in float: exact for seq<=8192, splits<=16 (fractional
//     parts >= 1/8192 >> max rounding error q*2^-23)

#define B_DIM 256
#define H_DIM 32
#define LOG2E 1.4426950408889634f

__global__ __launch_bounds__(128)
void splitkv_merge_kernel(const float* __restrict__ att_out,
                          const float* __restrict__ att_lse,
                          const int*   __restrict__ kv_indptr,
                          const int*   __restrict__ num_kv_splits,
                          float*       __restrict__ out)
{
    const unsigned hid  = (blockIdx.x * 128u + threadIdx.x) >> 5;   // (b,h)
    const unsigned lane = threadIdx.x & 31u;
    const unsigned b    = hid >> 5;                                 // H == 32

    const float4* __restrict__ src =
        reinterpret_cast<const float4*>(att_out) + hid * 512u + lane;

    // ---- cycle-0 issue group: everything independent of the div chain ----
    float4 v0 = src[0];          // s=0 (always valid)
    float4 v1 = src[32];         // s=1 (w=0 if nv==1)

    const float4* __restrict__ lse4 =
        reinterpret_cast<const float4*>(att_lse + hid * 16u);
    float4 l0 = lse4[0], l1 = lse4[1], l2 = lse4[2], l3 = lse4[3];

    const int ip0 = kv_indptr[b];
    const int ip1 = kv_indptr[b + 1];
    const unsigned splits = (unsigned)num_kv_splits[b];

    // ---- geometry via exact float ceil-divs ----
    const unsigned seq = (unsigned)(ip1 - ip0);
    const float fseq = __uint2float_rn(seq);
    const unsigned c1 = (unsigned)ceilf(fseq / __uint2float_rn(splits));
    const unsigned per_split = (c1 + 31u) & ~31u;
    const unsigned nv =
        (unsigned)ceilf(fseq / __uint2float_rn(per_split));   // 1..16 prefix

    // ---- issue batch1 loads (s=2..5) before the weight math ----
    float4 u0, u1, u2, u3;
    u0 = u1 = u2 = u3 = make_float4(0.f, 0.f, 0.f, 0.f);
    if (2u < nv) {
        u0 = src[2 * 32];
        if (3u < nv) u1 = src[3 * 32];
        if (4u < nv) u2 = src[4 * 32];
        if (5u < nv) u3 = src[5 * 32];
    }

    // ---- weights: per-lane in-register trees (no shuffles) ----
    float w[16] = { l0.x, l0.y, l0.z, l0.w,  l1.x, l1.y, l1.z, l1.w,
                    l2.x, l2.y, l2.z, l2.w,  l3.x, l3.y, l3.z, l3.w };
    #pragma unroll
    for (int s = 1; s < 16; ++s)              // s=0 always valid
        if ((unsigned)s >= nv) w[s] = -INFINITY;

    float m01 = w[0], m23 = w[1], m45 = w[2], m67 = w[3];   // max tree
    m01 = fmaxf(fmaxf(fmaxf(w[0], w[1]),  fmaxf(w[2], w[3])),
                fmaxf(fmaxf(w[4], w[5]),  fmaxf(w[6], w[7])));
    m23 = fmaxf(fmaxf(fmaxf(w[8], w[9]),  fmaxf(w[10], w[11])),
                fmaxf(fmaxf(w[12], w[13]), fmaxf(w[14], w[15])));
    const float m = fmaxf(m01, m23);
    (void)m45; (void)m67;

    #pragma unroll
    for (int s = 0; s < 16; ++s)              // exp2(-inf)=0 for masked
        w[s] = exp2f((w[s] - m) * LOG2E);

    // sum tree (depth 4)
    float e0 = (w[0] + w[1])  + (w[2] + w[3]);
    float e1 = (w[4] + w[5])  + (w[6] + w[7]);
    float e2 = (w[8] + w[9])  + (w[10] + w[11]);
    float e3 = (w[12] + w[13]) + (w[14] + w[15]);
    const float inv_esum = 1.0f / ((e0 + e1) + (e2 + e3));

    // ---- accumulate: weights are plain registers, no SHFL ----
    float4 acc;
    acc.x = fmaf(w[1], v1.x, w[0] * v0.x);
    acc.y = fmaf(w[1], v1.y, w[0] * v0.y);
    acc.z = fmaf(w[1], v1.z, w[0] * v0.z);
    acc.w = fmaf(w[1], v1.w, w[0] * v0.w);

    if (2u < nv) {
        // consume batch1 (s=2..5), then stream batches 2..3 + tail
        acc.x = fmaf(w[2], u0.x, acc.x); acc.y = fmaf(w[2], u0.y, acc.y);
        acc.z = fmaf(w[2], u0.z, acc.z); acc.w = fmaf(w[2], u0.w, acc.w);
        acc.x = fmaf(w[3], u1.x, acc.x); acc.y = fmaf(w[3], u1.y, acc.y);
        acc.z = fmaf(w[3], u1.z, acc.z); acc.w = fmaf(w[3], u1.w, acc.w);
        acc.x = fmaf(w[4], u2.x, acc.x); acc.y = fmaf(w[4], u2.y, acc.y);
        acc.z = fmaf(w[4], u2.z, acc.z); acc.w = fmaf(w[4], u2.w, acc.w);
        acc.x = fmaf(w[5], u3.x, acc.x); acc.y = fmaf(w[5], u3.y, acc.y);
        acc.z = fmaf(w[5], u3.z, acc.z); acc.w = fmaf(w[5], u3.w, acc.w);

        if (6u < nv) {
            float4 t0, t1, t2, t3;
            t0 = t1 = t2 = t3 = make_float4(0.f, 0.f, 0.f, 0.f);
            t0 = src[6 * 32];
            if (7u < nv) t1 = src[7 * 32];
            if (8u < nv) t2 = src[8 * 32];
            if (9u < nv) t3 = src[9 * 32];
            acc.x = fmaf(w[6], t0.x, acc.x); acc.y = fmaf(w[6], t0.y, acc.y);
            acc.z = fmaf(w[6], t0.z, acc.z); acc.w = fmaf(w[6], t0.w, acc.w);
            acc.x = fmaf(w[7], t1.x, acc.x); acc.y = fmaf(w[7], t1.y, acc.y);
            acc.z = fmaf(w[7], t1.z, acc.z); acc.w = fmaf(w[7], t1.w, acc.w);
            acc.x = fmaf(w[8], t2.x, acc.x); acc.y = fmaf(w[8], t2.y, acc.y);
            acc.z = fmaf(w[8], t2.z, acc.z); acc.w = fmaf(w[8], t2.w, acc.w);
            acc.x = fmaf(w[9], t3.x, acc.x); acc.y = fmaf(w[9], t3.y, acc.y);
            acc.z = fmaf(w[9], t3.z, acc.z); acc.w = fmaf(w[9], t3.w, acc.w);

            if (10u < nv) {
                float4 r0, r1, r2, r3;
                r0 = r1 = r2 = r3 = make_float4(0.f, 0.f, 0.f, 0.f);
                r0 = src[10 * 32];
                if (11u < nv) r1 = src[11 * 32];
                if (12u < nv) r2 = src[12 * 32];
                if (13u < nv) r3 = src[13 * 32];
                acc.x = fmaf(w[10], r0.x, acc.x); acc.y = fmaf(w[10], r0.y, acc.y);
                acc.z = fmaf(w[10], r0.z, acc.z); acc.w = fmaf(w[10], r0.w, acc.w);
                acc.x = fmaf(w[11], r1.x, acc.x); acc.y = fmaf(w[11], r1.y, acc.y);
                acc.z = fmaf(w[11], r1.z, acc.z); acc.w = fmaf(w[11], r1.w, acc.w);
                acc.x = fmaf(w[12], r2.x, acc.x); acc.y = fmaf(w[12], r2.y, acc.y);
                acc.z = fmaf(w[12], r2.z, acc.z); acc.w = fmaf(w[12], r2.w, acc.w);
                acc.x = fmaf(w[13], r3.x, acc.x); acc.y = fmaf(w[13], r3.y, acc.y);
                acc.z = fmaf(w[13], r3.z, acc.z); acc.w = fmaf(w[13], r3.w, acc.w);

                if (14u < nv) {
                    float4 q0, q1;
                    q0 = q1 = make_float4(0.f, 0.f, 0.f, 0.f);
                    q0 = src[14 * 32];
                    if (15u < nv) q1 = src[15 * 32];
                    acc.x = fmaf(w[14], q0.x, acc.x); acc.y = fmaf(w[14], q0.y, acc.y);
                    acc.z = fmaf(w[14], q0.z, acc.z); acc.w = fmaf(w[14], q0.w, acc.w);
                    acc.x = fmaf(w[15], q1.x, acc.x); acc.y = fmaf(w[15], q1.y, acc.y);
                    acc.z = fmaf(w[15], q1.z, acc.z); acc.w = fmaf(w[15], q1.w, acc.w);
                }
            }
        }
    }

    acc.x *= inv_esum;
    acc.y *= inv_esum;
    acc.z *= inv_esum;
    acc.w *= inv_esum;

    reinterpret_cast<float4*>(out)[hid * 32u + lane] = acc;
}

extern "C" void kernel_launch(void* const* d_in, const int* in_sizes, int n_in,
                              void* d_out, int out_size)
{
    const float* att_out       = (const float*)d_in[0];
    const float* att_lse       = (const float*)d_in[1];
    // d_in[2] = q, d_in[3] = v_buffer : unused (shape-only in the reference)
    const int*   kv_indptr     = (const int*)d_in[4];
    const int*   num_kv_splits = (const int*)d_in[5];
    float*       out           = (float*)d_out;

    // 8192 head-warps, 4 warps per 128-thread block -> 2048 blocks exact
    splitkv_merge_kernel<<<(B_DIM * H_DIM) / 4, 128>>>(att_out, att_lse,
                                                       kv_indptr, num_kv_splits, out);
}

// round 10
// speedup vs baseline: 1.1673x; 1.1636x over previous
#include <cuda_runtime.h>
#include <math.h>

// Split-KV (flash-decoding) stage-2 merge. B=256, H=32, S=16, D=128, fp32.
//
// R9 = R5 skeleton (the only shape that ever hit 8.9us: 1 warp/head,
// 8192 warps, shfl-held weights, 4-wide predicated batches, ~30 regs)
// plus ONLY register-neutral serial-chain cuts:
//   * LSE row + s=0/s=1 att_out rows issued UNCONDITIONALLY before the
//     geometry chain (predicate lane<16, not lane<nv) -> all memory in
//     flight at cycle 0; s=1 over-read (p~1/16) is killed by w=0
//   * float ceil-divs (exact: seq<=8192, splits<=16) instead of udiv emu
//   * half-warp reductions (offsets 8,4,2,1) + one broadcast: 9 SHFLs not 10
//   * 64-thread blocks (4096 exact) for finer tail packing
// Target: regs<=42, occ>=58%, dur ~7.5-8.1us.

#define B_DIM 256
#define H_DIM 32
#define LOG2E 1.4426950408889634f

__global__ __launch_bounds__(64)
void splitkv_merge_kernel(const float* __restrict__ att_out,
                          const float* __restrict__ att_lse,
                          const int*   __restrict__ kv_indptr,
                          const int*   __restrict__ num_kv_splits,
                          float*       __restrict__ out)
{
    const unsigned hid  = (blockIdx.x * 64u + threadIdx.x) >> 5;   // (b,h)
    const unsigned lane = threadIdx.x & 31u;
    const unsigned b    = hid >> 5;                                // H == 32

    const float4* __restrict__ src =
        reinterpret_cast<const float4*>(att_out) + hid * 512u + lane;

    // ---- cycle-0 issue group (nothing here depends on the div chain) ----
    float4 v0 = src[0];                         // s=0: always valid
    float4 v1 = src[32];                        // s=1: w=0 kills it if nv==1

    float lse = -INFINITY;
    if (lane < 16u)                             // no nv dependence
        lse = att_lse[hid * 16u + lane];

    const int ip0 = kv_indptr[b];
    const int ip1 = kv_indptr[b + 1];
    const unsigned splits = (unsigned)num_kv_splits[b];

    // ---- geometry via exact float ceil-divs ----
    const unsigned seq = (unsigned)(ip1 - ip0);
    const float fseq = __uint2float_rn(seq);
    const unsigned c1 = (unsigned)ceilf(fseq / __uint2float_rn(splits));
    const unsigned per_split = (c1 + 31u) & ~31u;
    const unsigned nv =
        (unsigned)ceilf(fseq / __uint2float_rn(per_split));  // 1..16 prefix

    // mask invalid splits (upper half already -inf)
    if (lane >= nv) lse = -INFINITY;

    // ---- weights: 4-step low-half reductions + single broadcast ----
    float m = lse;
    #pragma unroll
    for (int o = 8; o > 0; o >>= 1)
        m = fmaxf(m, __shfl_xor_sync(0xffffffffu, m, o));

    const float w = (lane < nv) ? exp2f((lse - m) * LOG2E) : 0.0f;

    float esum = w;
    #pragma unroll
    for (int o = 8; o > 0; o >>= 1)
        esum += __shfl_xor_sync(0xffffffffu, esum, o);

    const float inv_esum = __shfl_sync(0xffffffffu, 1.0f / esum, 0);

    // ---- accumulate: s=0,1 already in registers ----
    float ws0 = __shfl_sync(0xffffffffu, w, 0);
    float ws1 = __shfl_sync(0xffffffffu, w, 1);
    float4 acc;
    acc.x = fmaf(ws1, v1.x, ws0 * v0.x);
    acc.y = fmaf(ws1, v1.y, ws0 * v0.y);
    acc.z = fmaf(ws1, v1.z, ws0 * v0.z);
    acc.w = fmaf(ws1, v1.w, ws0 * v0.w);

    // ---- remaining splits: 4-wide front-batched predicated loads ----
    #pragma unroll
    for (int s0 = 2; s0 < 16; s0 += 4) {
        if (s0 < (int)nv) {                     // warp-uniform batch skip
            float4 t0, t1, t2, t3;
            t0 = t1 = t2 = t3 = make_float4(0.f, 0.f, 0.f, 0.f);
            t0 = src[s0 * 32];                  // s0 < nv guaranteed here
            if (s0 + 1 < (int)nv)                t1 = src[(s0 + 1) * 32];
            if ((s0 + 2 < 16) && (s0 + 2 < (int)nv)) t2 = src[(s0 + 2) * 32];
            if ((s0 + 3 < 16) && (s0 + 3 < (int)nv)) t3 = src[(s0 + 3) * 32];

            float ws;
            ws = __shfl_sync(0xffffffffu, w, s0 + 0);
            acc.x = fmaf(ws, t0.x, acc.x); acc.y = fmaf(ws, t0.y, acc.y);
            acc.z = fmaf(ws, t0.z, acc.z); acc.w = fmaf(ws, t0.w, acc.w);
            ws = __shfl_sync(0xffffffffu, w, s0 + 1);
            acc.x = fmaf(ws, t1.x, acc.x); acc.y = fmaf(ws, t1.y, acc.y);
            acc.z = fmaf(ws, t1.z, acc.z); acc.w = fmaf(ws, t1.w, acc.w);
            if (s0 + 2 < 16) {
                ws = __shfl_sync(0xffffffffu, w, s0 + 2);
                acc.x = fmaf(ws, t2.x, acc.x); acc.y = fmaf(ws, t2.y, acc.y);
                acc.z = fmaf(ws, t2.z, acc.z); acc.w = fmaf(ws, t2.w, acc.w);
                ws = __shfl_sync(0xffffffffu, w, s0 + 3);
                acc.x = fmaf(ws, t3.x, acc.x); acc.y = fmaf(ws, t3.y, acc.y);
                acc.z = fmaf(ws, t3.z, acc.z); acc.w = fmaf(ws, t3.w, acc.w);
            }
        }
    }

    acc.x *= inv_esum;
    acc.y *= inv_esum;
    acc.z *= inv_esum;
    acc.w *= inv_esum;

    reinterpret_cast<float4*>(out)[hid * 32u + lane] = acc;
}

extern "C" void kernel_launch(void* const* d_in, const int* in_sizes, int n_in,
                              void* d_out, int out_size)
{
    const float* att_out       = (const float*)d_in[0];
    const float* att_lse       = (const float*)d_in[1];
    // d_in[2] = q, d_in[3] = v_buffer : unused (shape-only in the reference)
    const int*   kv_indptr     = (const int*)d_in[4];
    const int*   num_kv_splits = (const int*)d_in[5];
    float*       out           = (float*)d_out;

    // 8192 head-warps, 2 warps per 64-thread block -> 4096 blocks exact
    splitkv_merge_kernel<<<(B_DIM * H_DIM) / 2, 64>>>(att_out, att_lse,
                                                      kv_indptr, num_kv_splits, out);
}